// round 7
// baseline (speedup 1.0000x reference)
#include <cuda_runtime.h>
#include <cuda_fp16.h>
#include <stdint.h>

#define BSZ 8
#define SEQ 4096
#define M_TOTAL 32768
#define NCHUNK 32
#define CHLEN 128

// Scratch (allocation-free)
__device__ float g_buf_k[(size_t)M_TOTAL * 1024];        // z  -> h0 (chunk-local)
__device__ float g_buf_th[(size_t)M_TOTAL * 1024];       // g  -> products p
__device__ float g_carry[(size_t)NCHUNK * BSZ * 1024];
__device__ __half g_ah[(size_t)M_TOTAL * 1024];          // A fp16 (x, then h)
__device__ __half g_wf[(size_t)3072 * 1024];             // [Wz;Wh;Wo] fp16

// ---------------------------------------------------------------------------
__device__ __forceinline__ uint32_t smem_u32(const void* p) {
    uint32_t a;
    asm("{ .reg .u64 t; cvta.to.shared.u64 t, %1; cvt.u32.u64 %0, t; }" : "=r"(a) : "l"(p));
    return a;
}
__device__ __forceinline__ void ldsm4(uint32_t* r, uint32_t addr) {
    asm volatile("ldmatrix.sync.aligned.m8n8.x4.shared.b16 {%0,%1,%2,%3}, [%4];"
                 : "=r"(r[0]), "=r"(r[1]), "=r"(r[2]), "=r"(r[3]) : "r"(addr));
}
__device__ __forceinline__ void mma16816(float* d, const uint32_t* a, uint32_t b0, uint32_t b1) {
    asm volatile(
        "mma.sync.aligned.m16n8k16.row.col.f32.f16.f16.f32 "
        "{%0,%1,%2,%3}, {%4,%5,%6,%7}, {%8,%9}, {%0,%1,%2,%3};"
        : "+f"(d[0]), "+f"(d[1]), "+f"(d[2]), "+f"(d[3])
        : "r"(a[0]), "r"(a[1]), "r"(a[2]), "r"(a[3]), "r"(b0), "r"(b1));
}
__device__ __forceinline__ void cp16(uint32_t saddr, const void* gaddr) {
    asm volatile("cp.async.cg.shared.global [%0], [%1], 16;" :: "r"(saddr), "l"(gaddr));
}
__device__ __forceinline__ uint2 pack_h4(__half a, __half b, __half c, __half d) {
    uint2 r;
    r.x = ((uint32_t)__half_as_ushort(b) << 16) | __half_as_ushort(a);
    r.y = ((uint32_t)__half_as_ushort(d) << 16) | __half_as_ushort(c);
    return r;
}
__device__ __forceinline__ float sigmoidf_fast(float v) {
    return 1.0f / (1.0f + __expf(-v));
}

// SMEM: [0..512) bias; stages at 1024, 16KB each (A 8K | W 8K)
#define STAGE_BYTES 16384
#define NSTAGE 4
#define SMEM_TOTAL (1024 + NSTAGE * STAGE_BYTES)   // 66560

// ---------------------------------------------------------------------------
// conversions
// ---------------------------------------------------------------------------
__global__ void __launch_bounds__(256) split_w_kernel(
    const float4* __restrict__ Wz, const float4* __restrict__ Wh,
    const float4* __restrict__ Wo, uint2* __restrict__ dst)
{
    const int i = blockIdx.x * 256 + threadIdx.x;   // 0 .. 786431
    const int mat = i >> 18;
    const int off = i & 262143;
    const float4* src = (mat == 0) ? Wz : (mat == 1) ? Wh : Wo;
    const float4 v = src[off];
    dst[i] = pack_h4(__float2half_rn(v.x), __float2half_rn(v.y),
                     __float2half_rn(v.z), __float2half_rn(v.w));
}

__global__ void __launch_bounds__(256) split_a_kernel(
    const float4* __restrict__ src, uint2* __restrict__ dh, int base)
{
    const int i = base + blockIdx.x * 256 + threadIdx.x;
    const float4 v = src[i];
    dh[i] = pack_h4(__float2half_rn(v.x), __float2half_rn(v.y),
                    __float2half_rn(v.z), __float2half_rn(v.w));
}

// ---------------------------------------------------------------------------
// HMMA GEMM fp16xfp16->fp32: C = act(A * W^T + bias)
// act==1: first-half outputs get sigmoid, second-half get g().
// CTA 128x128, Kc=32, 4-stage cp.async, 8 warps of 64x32, 2 CTA/SM.
// ---------------------------------------------------------------------------
__device__ __forceinline__ void load_stage(
    uint32_t st,
    const __half* __restrict__ Ah, const __half* __restrict__ Wf,
    int m0, int brow0, int k0, int tid)
{
    #pragma unroll
    for (int i = 0; i < 4; ++i) {
        const int id = i * 256 + tid;
        const int sec = id >> 9;             // 0 = A, 1 = W
        const int cid = id & 511;
        const int r = cid >> 2;
        const int c = cid & 3;
        const __half* gsrc = (sec == 0)
            ? Ah + (size_t)(m0 + r) * 1024 + k0 + c * 8
            : Wf + (size_t)(brow0 + r) * 1024 + k0 + c * 8;
        const uint32_t saddr = st + sec * 8192 + r * 64 + ((uint32_t)(c ^ ((r >> 1) & 3)) << 4);
        cp16(saddr, gsrc);
    }
}

__global__ void __launch_bounds__(256, 2) gemm_hmma(
    const __half* __restrict__ Ah, const __half* __restrict__ Wf, int wrow_off,
    const float* __restrict__ b0, const float* __restrict__ b1,
    float* __restrict__ C0, float* __restrict__ C1, int nsplit, int act)
{
    extern __shared__ char smem[];
    const uint32_t sbase = smem_u32(smem);
    float* sbias = (float*)smem;

    const int tid = threadIdx.x;
    const int wid = tid >> 5;
    const int lane = tid & 31;
    const int m0 = blockIdx.y * 128;
    const int n0 = blockIdx.x * 128;
    const bool second = (n0 >= nsplit);
    const int nn = second ? (n0 - nsplit) : n0;
    const float* bias = second ? b1 : b0;
    float* C = second ? C1 : C0;
    const int brow0 = wrow_off + n0;

    if (tid < 128) sbias[tid] = bias[nn + tid];

    #pragma unroll
    for (int s = 0; s < NSTAGE - 1; ++s) {
        load_stage(sbase + 1024 + s * STAGE_BYTES, Ah, Wf, m0, brow0, s * 32, tid);
        asm volatile("cp.async.commit_group;" ::: "memory");
    }

    float acc[4][4][4];
    #pragma unroll
    for (int a = 0; a < 4; ++a)
        #pragma unroll
        for (int b = 0; b < 4; ++b)
            #pragma unroll
            for (int c = 0; c < 4; ++c)
                acc[a][b][c] = 0.0f;

    const int wm = (wid >> 2) * 64;
    const int wn = (wid & 3) * 32;
    const int sel = lane & 15;
    const int cext = lane >> 4;

    #pragma unroll 1
    for (int kt = 0; kt < 32; ++kt) {
        asm volatile("cp.async.wait_group 2;" ::: "memory");
        __syncthreads();

        const uint32_t st = sbase + 1024 + (kt & 3) * STAGE_BYTES;
        #pragma unroll
        for (int ks = 0; ks < 2; ++ks) {
            const int cch = ks * 2 + cext;
            uint32_t wfr[2][4];
            #pragma unroll
            for (int ni2 = 0; ni2 < 2; ++ni2) {
                const int n = wn + ni2 * 16 + sel;
                const uint32_t off = (uint32_t)(n * 64) + ((uint32_t)(cch ^ ((n >> 1) & 3)) << 4);
                ldsm4(wfr[ni2], st + 8192 + off);
            }
            #pragma unroll
            for (int mi = 0; mi < 4; ++mi) {
                const int m = wm + mi * 16 + sel;
                const uint32_t off = (uint32_t)(m * 64) + ((uint32_t)(cch ^ ((m >> 1) & 3)) << 4);
                uint32_t ahf[4];
                ldsm4(ahf, st + off);
                #pragma unroll
                for (int ni = 0; ni < 4; ++ni) {
                    const int ni2 = ni >> 1, jj = ni & 1;
                    mma16816(acc[mi][ni], ahf, wfr[ni2][jj], wfr[ni2][jj + 2]);
                }
            }
        }

        if (kt + NSTAGE - 1 < 32) {
            load_stage(sbase + 1024 + ((kt + NSTAGE - 1) & 3) * STAGE_BYTES,
                       Ah, Wf, m0, brow0, (kt + NSTAGE - 1) * 32, tid);
        }
        asm volatile("cp.async.commit_group;" ::: "memory");
    }

    #pragma unroll
    for (int mi = 0; mi < 4; ++mi) {
        const int gm = m0 + wm + mi * 16 + (lane >> 2);
        #pragma unroll
        for (int ni = 0; ni < 4; ++ni) {
            const int col = wn + ni * 8 + (lane & 3) * 2;
            const float bv0 = sbias[col];
            const float bv1 = sbias[col + 1];
            float* p0 = C + (size_t)gm * 1024 + nn + col;
            #pragma unroll
            for (int hrow = 0; hrow < 2; ++hrow) {
                float2 v;
                v.x = acc[mi][ni][2 * hrow + 0] + bv0;
                v.y = acc[mi][ni][2 * hrow + 1] + bv1;
                if (act) {
                    if (!second) {             // z = sigmoid(k)
                        v.x = sigmoidf_fast(v.x);
                        v.y = sigmoidf_fast(v.y);
                    } else {                   // g(th)
                        v.x = (v.x >= 0.0f) ? (v.x + 0.5f) : sigmoidf_fast(v.x);
                        v.y = (v.y >= 0.0f) ? (v.y + 0.5f) : sigmoidf_fast(v.y);
                    }
                }
                *(float2*)(p0 + hrow * 8 * 1024) = v;
            }
        }
    }
}

// ---------------------------------------------------------------------------
// Chunked linear-recurrence scan (transcendental-free)
// zb holds z, gb holds g. Overwrites zb with chunk-local h0, gb with product p.
// ---------------------------------------------------------------------------
__global__ void __launch_bounds__(256) scan_stage1(float4* __restrict__ zb,
                                                   float4* __restrict__ gb)
{
    const int t = blockIdx.x * 256 + threadIdx.x;       // 0 .. 65535
    const int chunk = t >> 11;                           // 0..31
    const int r = t & 2047;                              // b*256 + h4
    const int b = r >> 8;
    const int h4 = r & 255;
    size_t off = ((size_t)b * SEQ + chunk * CHLEN) * 256 + h4;   // in float4 units

    float4 h = make_float4(0.f, 0.f, 0.f, 0.f);
    float4 p = make_float4(1.f, 1.f, 1.f, 1.f);
    #pragma unroll 4
    for (int s = 0; s < CHLEN; ++s, off += 256) {
        const float4 z = zb[off];
        const float4 g = gb[off];
        const float ax = 1.0f - z.x, ay = 1.0f - z.y, az = 1.0f - z.z, aw = 1.0f - z.w;
        h.x = fmaf(ax, h.x, z.x * g.x);
        h.y = fmaf(ay, h.y, z.y * g.y);
        h.z = fmaf(az, h.z, z.z * g.z);
        h.w = fmaf(aw, h.w, z.w * g.w);
        p.x *= ax; p.y *= ay; p.z *= az; p.w *= aw;
        zb[off] = h;
        gb[off] = p;
    }
}

__global__ void __launch_bounds__(256) scan_stage2(const float* __restrict__ kb,
                                                   const float* __restrict__ th,
                                                   float* __restrict__ carry)
{
    const int cid = blockIdx.x * 256 + threadIdx.x;
    if (cid >= BSZ * 1024) return;
    const int b = cid >> 10;
    const int hh = cid & 1023;
    float c = 0.0f;
    #pragma unroll 1
    for (int ck = 0; ck < NCHUNK; ++ck) {
        carry[(size_t)ck * 8192 + cid] = c;
        const size_t off = ((size_t)b * SEQ + ck * CHLEN + (CHLEN - 1)) * 1024 + hh;
        c = fmaf(th[off], c, kb[off]);
    }
}

// stage3: finalize h and emit fp16 directly
__global__ void __launch_bounds__(256) scan_stage3(const float* __restrict__ kb,
                                                   const float* __restrict__ th,
                                                   const float* __restrict__ carry,
                                                   uint2* __restrict__ dh)
{
    const size_t i4 = (size_t)blockIdx.x * 256 + threadIdx.x;
    const size_t e = i4 * 4;
    const size_t m = e >> 10;
    const int hh = (int)(e & 1023);
    const int b = (int)(m >> 12);
    const int s = (int)(m & 4095);
    const int ck = s >> 7;

    float4 h0 = *(const float4*)(kb + e);
    const float4 p = *(const float4*)(th + e);
    const float4 cv = *(const float4*)(carry + (size_t)ck * 8192 + b * 1024 + hh);
    h0.x = fmaf(p.x, cv.x, h0.x);
    h0.y = fmaf(p.y, cv.y, h0.y);
    h0.z = fmaf(p.z, cv.z, h0.z);
    h0.w = fmaf(p.w, cv.w, h0.w);

    dh[i4] = pack_h4(__float2half_rn(h0.x), __float2half_rn(h0.y),
                     __float2half_rn(h0.z), __float2half_rn(h0.w));
}

// ---------------------------------------------------------------------------
extern "C" void kernel_launch(void* const* d_in, const int* in_sizes, int n_in,
                              void* d_out, int out_size)
{
    const float* x  = (const float*)d_in[0];
    const float* Wz = (const float*)d_in[1];
    const float* bz = (const float*)d_in[2];
    const float* Wh = (const float*)d_in[3];
    const float* bh = (const float*)d_in[4];
    const float* Wo = (const float*)d_in[5];
    const float* bo = (const float*)d_in[6];
    float* out = (float*)d_out;

    float *kbuf, *thbuf, *carry;
    __half *ah, *wf;
    cudaGetSymbolAddress((void**)&kbuf,  g_buf_k);
    cudaGetSymbolAddress((void**)&thbuf, g_buf_th);
    cudaGetSymbolAddress((void**)&carry, g_carry);
    cudaGetSymbolAddress((void**)&ah, g_ah);
    cudaGetSymbolAddress((void**)&wf, g_wf);

    static bool attr_done = false;
    if (!attr_done) {
        cudaFuncSetAttribute(gemm_hmma,
                             cudaFuncAttributeMaxDynamicSharedMemorySize, SMEM_TOTAL);
        attr_done = true;
    }

    // 1: fused W conversion (fp16)
    split_w_kernel<<<3072, 256>>>((const float4*)Wz, (const float4*)Wh,
                                  (const float4*)Wo, (uint2*)wf);

    // 2,3: x conversion (fp16), two halves (keeps GEMM1 at launch #4 for ncu)
    const int x4 = (int)((size_t)M_TOTAL * 1024 / 4);   // 8388608
    split_a_kernel<<<x4 / 512, 256>>>((const float4*)x, (uint2*)ah, 0);
    split_a_kernel<<<x4 / 512, 256>>>((const float4*)x, (uint2*)ah, x4 / 2);

    // 4: fused input GEMMs with fused activations: z | g  (N = 2048 logical)
    {
        dim3 grid(16, 256);
        gemm_hmma<<<grid, 256, SMEM_TOTAL>>>(ah, wf, 0, bz, bh, kbuf, thbuf, 1024, 1);
    }

    // 5-7: chunked scan (transcendental-free stage1; stage3 emits fp16 h)
    scan_stage1<<<65536 / 256, 256>>>((float4*)kbuf, (float4*)thbuf);
    scan_stage2<<<(BSZ * 1024) / 256, 256>>>(kbuf, thbuf, carry);
    scan_stage3<<<x4 / 256, 256>>>(kbuf, thbuf, carry, (uint2*)ah);

    // 8: out = h Wo^T + bo
    {
        dim3 grid(8, 256);
        gemm_hmma<<<grid, 256, SMEM_TOTAL>>>(ah, wf, 2048, bo, bo, out, out, 1 << 30, 0);
    }
}